// round 7
// baseline (speedup 1.0000x reference)
#include <cuda_runtime.h>
#include <cuda_fp16.h>
#include <cstdint>

#define FIN   64
#define FOUT  64
#define FH    128
#define LATD  512
#define NB    16
#define HW    16384
#define KTOT  53760
#define WS    53248   // fp16 elements of packed weights per sample (single-term)

// per-sample fp16 element offsets of fragment-ordered weight buffers
#define WIN_O   0        // O=128 I=64  (8192 ele)
#define WMIDA_O 8192     // O=128 I=128 (16384)
#define WMIDB_O 24576    // O=128 I=128 (16384)
#define WOUT_O  40960    // O=64 I=128  (8192)
#define WSH_O   49152    // O=64 I=64   (4096)

__device__ __align__(16) __half g_wh[NB * WS];
__device__ __align__(16) float g_bias[NB * 512];

// ---------------- helpers ----------------
__device__ __forceinline__ uint32_t pack_f16x2(float f0, float f1) {
    uint32_t r;
    asm("cvt.rn.f16x2.f32 %0, %1, %2;" : "=r"(r) : "f"(f1), "f"(f0));
    return r;
}

__device__ __forceinline__ void mma16816(float d[4],
    const uint32_t a[4], uint32_t b0, uint32_t b1)
{
    asm volatile(
        "mma.sync.aligned.m16n8k16.row.col.f32.f16.f16.f32 "
        "{%0,%1,%2,%3}, {%4,%5,%6,%7}, {%8,%9}, {%0,%1,%2,%3};"
        : "+f"(d[0]), "+f"(d[1]), "+f"(d[2]), "+f"(d[3])
        : "r"(a[0]), "r"(a[1]), "r"(a[2]), "r"(a[3]), "r"(b0), "r"(b1));
}

// ============================================================
// Kernel A: hypernetwork GEMM (scalar FFMA core, float4 LDS)
// + fp16 pack into mma.sync B-fragment order.
// ============================================================
__global__ __launch_bounds__(128) void hyper_kernel(
    const float* __restrict__ lat,
    const float* __restrict__ Wm,
    const float* __restrict__ bias)
{
    __shared__ __align__(16) float slat[NB][LATD];   // 32 KB
    for (int i = threadIdx.x; i < NB * LATD; i += 128)
        slat[i >> 9][i & 511] = lat[i];
    __syncthreads();

    int k = blockIdx.x * 128 + threadIdx.x;   // 420*128 == 53760 exact

    float acc[NB];
#pragma unroll
    for (int s = 0; s < NB; s++) acc[s] = 0.f;

    const float4* wr = (const float4*)(Wm + (size_t)k * LATD);
#pragma unroll 4
    for (int l4 = 0; l4 < LATD / 4; l4++) {
        float4 w = wr[l4];
#pragma unroll
        for (int s = 0; s < NB; s++) {
            float4 lv = ((const float4*)slat[s])[l4];
            acc[s] = fmaf(w.x, lv.x, acc[s]);
            acc[s] = fmaf(w.y, lv.y, acc[s]);
            acc[s] = fmaf(w.z, lv.z, acc[s]);
            acc[s] = fmaf(w.w, lv.w, acc[s]);
        }
    }

    const float RS128 = 0.08838834764831845f;  // 1/sqrt(128)
    const float RS64  = 0.125f;                // 1/sqrt(64)
    float bk = bias[k];

    // map k -> (layer, o, i) -> fragment element index
    bool isBias = false;
    float scale = 1.f;
    int o = 0, i = 0, I = 0, base = 0;
    if (k < 8192) {
        o = k >> 6; i = k & 63; I = 64;
        base = WIN_O; scale = RS128;
    } else if (k < 24576) {
        int idx = k - 8192; o = idx >> 7; i = idx & 127; I = 128;
        base = WMIDA_O; scale = RS128;
    } else if (k < 40960) {
        int idx = k - 24576; o = idx >> 7; i = idx & 127; I = 128;
        base = WMIDB_O; scale = RS128;
    } else if (k < 49152) {
        int idx = k - 40960; o = idx >> 7; i = idx & 127; I = 128;
        base = WOUT_O; scale = RS64;
    } else if (k < 53248) {
        int idx = k - 49152; o = idx >> 6; i = idx & 63; I = 64;
        base = WSH_O; scale = RS64;
    } else {
        isBias = true;
    }

    int fel = 0;
    if (!isBias) {
        int KT = I / 16;
        int nt = o >> 3, kt = i >> 4;
        int tl = (o & 7) * 4 + ((i & 7) >> 1);          // lane
        int el = (((i >> 3) & 1) << 1) | (i & 1);       // elem within 4-group
        fel = base + ((nt * KT + kt) * 32 + tl) * 4 + el;
    }

#pragma unroll
    for (int s = 0; s < NB; s++) {
        if (isBias) {
            g_bias[s * 512 + (k - 53248)] = acc[s] + bk;
        } else {
            g_wh[(size_t)s * WS + fel] = __float2half_rn((acc[s] + bk) * scale);
        }
    }
}

// ============================================================
// Kernel B: mma.sync fused block, fp16 single-term weights,
// M=32 per warp, 4-nt transient accumulator chunks (bias folded),
// activations register-resident fp16.
// ============================================================

// one fused hidden layer producing 128 channels
template <int KT>
__device__ __forceinline__ void layer_fused(
    const uint32_t (*A0)[4], const uint32_t (*A1)[4],
    uint32_t (*N0)[4], uint32_t (*N1)[4],
    const char* __restrict__ sm, int bOff,
    const float* __restrict__ bsm, int lane, int tig)
{
#pragma unroll
    for (int c = 0; c < 4; c++) {        // chunk = 4 nt = 32 channels
        float D[2][4][4];
#pragma unroll
        for (int j = 0; j < 4; j++) {
            int nt = c * 4 + j;
            float b0 = bsm[nt * 8 + tig * 2];
            float b1 = bsm[nt * 8 + tig * 2 + 1];
#pragma unroll
            for (int m = 0; m < 2; m++) {
                D[m][j][0] = b0; D[m][j][1] = b1;
                D[m][j][2] = b0; D[m][j][3] = b1;
            }
        }
#pragma unroll
        for (int kt = 0; kt < KT; kt++) {
            uint2 bf[4];
#pragma unroll
            for (int j = 0; j < 4; j++) {
                int fo = (((c * 4 + j) * KT + kt) * 32 + lane) * 8;
                bf[j] = *(const uint2*)(sm + bOff + fo);
            }
#pragma unroll
            for (int j = 0; j < 4; j++) mma16816(D[0][j], A0[kt], bf[j].x, bf[j].y);
#pragma unroll
            for (int j = 0; j < 4; j++) mma16816(D[1][j], A1[kt], bf[j].x, bf[j].y);
        }
        // relu + fp16 pack -> next-layer A fragments
#pragma unroll
        for (int m = 0; m < 2; m++) {
            uint32_t (*N)[4] = m ? N1 : N0;
#pragma unroll
            for (int j = 0; j < 4; j++) {
                int nt = c * 4 + j;
                N[nt >> 1][(nt & 1) * 2 + 0] =
                    pack_f16x2(fmaxf(D[m][j][0], 0.f), fmaxf(D[m][j][1], 0.f));
                N[nt >> 1][(nt & 1) * 2 + 1] =
                    pack_f16x2(fmaxf(D[m][j][2], 0.f), fmaxf(D[m][j][3], 0.f));
            }
        }
    }
}

__global__ __launch_bounds__(256, 1) void conv_kernel(
    const float* __restrict__ x, float* __restrict__ out)
{
    extern __shared__ __align__(16) char smem[];
    const float* bsm = (const float*)(smem + WS * 2);

    const int tid = threadIdx.x;
    const int w = tid >> 5, lane = tid & 31;
    const int gid = lane >> 2, tig = lane & 3;
    const int b  = blockIdx.x / 9;
    const int cs = blockIdx.x % 9;

    // stage all fragment-ordered weights (106496 B) + biases (2 KB)
    {
        const uint4* src = (const uint4*)(g_wh + (size_t)b * WS);
        uint4* dst = (uint4*)smem;
        for (int i = tid; i < WS / 8; i += 256) dst[i] = src[i];
        const float4* bsrc = (const float4*)(g_bias + b * 512);
        float4* bdst = (float4*)(smem + WS * 2);
        if (tid < 128) bdst[tid] = bsrc[tid];
    }
    __syncthreads();

    const float* xb = x + (size_t)b * FIN * HW;
    float* ob = out + (size_t)b * FOUT * HW;

    uint32_t X[2][4][4];
    uint32_t Abuf[2][2][8][4];   // ping-pong [pp][half][kt][4]

    for (int t = cs; t < 64; t += 9) {
        const int base = t * 256 + w * 32;

        // ---- load x as fp16 A fragments for both m16 halves ----
#pragma unroll
        for (int m = 0; m < 2; m++) {
            const int px_lo = base + m * 16 + gid;
            const int px_hi = px_lo + 8;
#pragma unroll
            for (int kt = 0; kt < 4; kt++) {
                const float* xp = xb + (size_t)(kt * 16 + tig * 2) * HW;
                X[m][kt][0] = pack_f16x2(xp[px_lo],          xp[HW + px_lo]);
                X[m][kt][1] = pack_f16x2(xp[px_hi],          xp[HW + px_hi]);
                X[m][kt][2] = pack_f16x2(xp[8 * HW + px_lo], xp[9 * HW + px_lo]);
                X[m][kt][3] = pack_f16x2(xp[8 * HW + px_hi], xp[9 * HW + px_hi]);
            }
        }

        // ---- layer in (KT=4): x -> Abuf[0] ----
        layer_fused<4>(X[0], X[1], Abuf[0][0], Abuf[0][1],
                       smem, WIN_O * 2, bsm + 0, lane, tig);
        // ---- layer mida (KT=8): Abuf[0] -> Abuf[1] ----
        layer_fused<8>(Abuf[0][0], Abuf[0][1], Abuf[1][0], Abuf[1][1],
                       smem, WMIDA_O * 2, bsm + 128, lane, tig);
        // ---- layer midb (KT=8): Abuf[1] -> Abuf[0] ----
        layer_fused<8>(Abuf[1][0], Abuf[1][1], Abuf[0][0], Abuf[0][1],
                       smem, WMIDB_O * 2, bsm + 256, lane, tig);

        // ---- out layer: Wout @ h + Wshort @ x, 64 ch, store ----
#pragma unroll
        for (int c = 0; c < 2; c++) {
            float D[2][4][4];
#pragma unroll
            for (int j = 0; j < 4; j++) {
                int ch = (c * 4 + j) * 8 + tig * 2;
                float b0 = bsm[384 + ch]     + bsm[448 + ch];
                float b1 = bsm[384 + ch + 1] + bsm[448 + ch + 1];
#pragma unroll
                for (int m = 0; m < 2; m++) {
                    D[m][j][0] = b0; D[m][j][1] = b1;
                    D[m][j][2] = b0; D[m][j][3] = b1;
                }
            }
#pragma unroll
            for (int kt = 0; kt < 8; kt++) {
                uint2 bf[4];
#pragma unroll
                for (int j = 0; j < 4; j++) {
                    int fo = (((c * 4 + j) * 8 + kt) * 32 + lane) * 8;
                    bf[j] = *(const uint2*)(smem + WOUT_O * 2 + fo);
                }
#pragma unroll
                for (int j = 0; j < 4; j++) mma16816(D[0][j], Abuf[0][0][kt], bf[j].x, bf[j].y);
#pragma unroll
                for (int j = 0; j < 4; j++) mma16816(D[1][j], Abuf[0][1][kt], bf[j].x, bf[j].y);
            }
#pragma unroll
            for (int kt = 0; kt < 4; kt++) {
                uint2 bf[4];
#pragma unroll
                for (int j = 0; j < 4; j++) {
                    int fo = (((c * 4 + j) * 4 + kt) * 32 + lane) * 8;
                    bf[j] = *(const uint2*)(smem + WSH_O * 2 + fo);
                }
#pragma unroll
                for (int j = 0; j < 4; j++) mma16816(D[0][j], X[0][kt], bf[j].x, bf[j].y);
#pragma unroll
                for (int j = 0; j < 4; j++) mma16816(D[1][j], X[1][kt], bf[j].x, bf[j].y);
            }
            // store 32 channels x 32 pixels
#pragma unroll
            for (int m = 0; m < 2; m++) {
                const int px_lo = base + m * 16 + gid;
                const int px_hi = px_lo + 8;
#pragma unroll
                for (int j = 0; j < 4; j++) {
                    int ch = (c * 4 + j) * 8 + tig * 2;
                    float* op = ob + (size_t)ch * HW;
                    op[px_lo]      = D[m][j][0];
                    op[HW + px_lo] = D[m][j][1];
                    op[px_hi]      = D[m][j][2];
                    op[HW + px_hi] = D[m][j][3];
                }
            }
        }
    }
}

// ============================================================
extern "C" void kernel_launch(void* const* d_in, const int* in_sizes, int n_in,
                              void* d_out, int out_size)
{
    (void)in_sizes; (void)n_in; (void)out_size;
    const float* x    = (const float*)d_in[0];
    const float* lat  = (const float*)d_in[1];
    const float* W    = (const float*)d_in[2];
    const float* bias = (const float*)d_in[3];
    float* out = (float*)d_out;

    hyper_kernel<<<KTOT / 128, 128>>>(lat, W, bias);

    cudaFuncSetAttribute(conv_kernel,
                         cudaFuncAttributeMaxDynamicSharedMemorySize, 110592);
    conv_kernel<<<16 * 9, 256, 110592>>>(x, out);
}

// round 8
// speedup vs baseline: 2.7083x; 2.7083x over previous
#include <cuda_runtime.h>
#include <cuda_fp16.h>
#include <cstdint>

#define FIN   64
#define FOUT  64
#define FH    128
#define LATD  512
#define NB    16
#define HW    16384
#define KTOT  53760
#define WS    53248   // fp16 elements of packed weights per sample (single-term)

// per-sample fp16 element offsets of fragment-ordered weight buffers
#define WIN_O   0        // O=128 I=64  (8192 ele)
#define WMIDA_O 8192     // O=128 I=128 (16384)
#define WMIDB_O 24576    // O=128 I=128 (16384)
#define WOUT_O  40960    // O=64 I=128  (8192)
#define WSH_O   49152    // O=64 I=64   (4096)

__device__ __align__(16) __half g_wh[NB * WS];
__device__ __align__(16) float g_bias[NB * 512];

// ---------------- helpers ----------------
__device__ __forceinline__ uint32_t pack_f16x2(float f0, float f1) {
    uint32_t r;
    asm("cvt.rn.f16x2.f32 %0, %1, %2;" : "=r"(r) : "f"(f1), "f"(f0));
    return r;
}

__device__ __forceinline__ void mma16816(float d[4],
    const uint32_t a[4], uint32_t b0, uint32_t b1)
{
    asm volatile(
        "mma.sync.aligned.m16n8k16.row.col.f32.f16.f16.f32 "
        "{%0,%1,%2,%3}, {%4,%5,%6,%7}, {%8,%9}, {%0,%1,%2,%3};"
        : "+f"(d[0]), "+f"(d[1]), "+f"(d[2]), "+f"(d[3])
        : "r"(a[0]), "r"(a[1]), "r"(a[2]), "r"(a[3]), "r"(b0), "r"(b1));
}

// ============================================================
// Kernel A: hypernetwork GEMM (scalar FFMA core, float4 LDS)
// + fp16 pack into mma.sync B-fragment order.
// ============================================================
__global__ __launch_bounds__(128) void hyper_kernel(
    const float* __restrict__ lat,
    const float* __restrict__ Wm,
    const float* __restrict__ bias)
{
    __shared__ __align__(16) float slat[NB][LATD];   // 32 KB
    for (int i = threadIdx.x; i < NB * LATD; i += 128)
        slat[i >> 9][i & 511] = lat[i];
    __syncthreads();

    int k = blockIdx.x * 128 + threadIdx.x;   // 420*128 == 53760 exact

    float acc[NB];
#pragma unroll
    for (int s = 0; s < NB; s++) acc[s] = 0.f;

    const float4* wr = (const float4*)(Wm + (size_t)k * LATD);
#pragma unroll 4
    for (int l4 = 0; l4 < LATD / 4; l4++) {
        float4 w = wr[l4];
#pragma unroll
        for (int s = 0; s < NB; s++) {
            float4 lv = ((const float4*)slat[s])[l4];
            acc[s] = fmaf(w.x, lv.x, acc[s]);
            acc[s] = fmaf(w.y, lv.y, acc[s]);
            acc[s] = fmaf(w.z, lv.z, acc[s]);
            acc[s] = fmaf(w.w, lv.w, acc[s]);
        }
    }

    const float RS128 = 0.08838834764831845f;  // 1/sqrt(128)
    const float RS64  = 0.125f;                // 1/sqrt(64)
    float bk = bias[k];

    // map k -> (layer, o, i) -> fragment element index
    bool isBias = false;
    float scale = 1.f;
    int o = 0, i = 0, I = 0, base = 0;
    if (k < 8192) {
        o = k >> 6; i = k & 63; I = 64;
        base = WIN_O; scale = RS128;
    } else if (k < 24576) {
        int idx = k - 8192; o = idx >> 7; i = idx & 127; I = 128;
        base = WMIDA_O; scale = RS128;
    } else if (k < 40960) {
        int idx = k - 24576; o = idx >> 7; i = idx & 127; I = 128;
        base = WMIDB_O; scale = RS128;
    } else if (k < 49152) {
        int idx = k - 40960; o = idx >> 7; i = idx & 127; I = 128;
        base = WOUT_O; scale = RS64;
    } else if (k < 53248) {
        int idx = k - 49152; o = idx >> 6; i = idx & 63; I = 64;
        base = WSH_O; scale = RS64;
    } else {
        isBias = true;
    }

    int fel = 0;
    if (!isBias) {
        int KT = I / 16;
        int nt = o >> 3, kt = i >> 4;
        int tl = (o & 7) * 4 + ((i & 7) >> 1);          // lane
        int el = (((i >> 3) & 1) << 1) | (i & 1);       // elem within 4-group
        fel = base + ((nt * KT + kt) * 32 + tl) * 4 + el;
    }

#pragma unroll
    for (int s = 0; s < NB; s++) {
        if (isBias) {
            g_bias[s * 512 + (k - 53248)] = acc[s] + bk;
        } else {
            g_wh[(size_t)s * WS + fel] = __float2half_rn((acc[s] + bk) * scale);
        }
    }
}

// ============================================================
// Kernel B: mma.sync fused block, fp16 single-term weights,
// M=32 per warp, 2-nt transient accumulator chunks (bias folded;
// proven no-spill structure from R6), activations register-resident.
// ============================================================

// one fused hidden layer producing 128 channels
template <int KT>
__device__ __forceinline__ void layer_fused(
    const uint32_t (*A0)[4], const uint32_t (*A1)[4],
    uint32_t (*N0)[4], uint32_t (*N1)[4],
    const char* __restrict__ sm, int bOff,
    const float* __restrict__ bsm, int lane, int tig)
{
#pragma unroll
    for (int c = 0; c < 8; c++) {        // chunk = 2 nt = 16 channels
        float D[2][2][4];
#pragma unroll
        for (int j = 0; j < 2; j++) {
            int nt = c * 2 + j;
            float b0 = bsm[nt * 8 + tig * 2];
            float b1 = bsm[nt * 8 + tig * 2 + 1];
#pragma unroll
            for (int m = 0; m < 2; m++) {
                D[m][j][0] = b0; D[m][j][1] = b1;
                D[m][j][2] = b0; D[m][j][3] = b1;
            }
        }
#pragma unroll
        for (int kt = 0; kt < KT; kt++) {
            uint2 bf[2];
#pragma unroll
            for (int j = 0; j < 2; j++) {
                int fo = (((c * 2 + j) * KT + kt) * 32 + lane) * 8;
                bf[j] = *(const uint2*)(sm + bOff + fo);
            }
#pragma unroll
            for (int j = 0; j < 2; j++) {
                mma16816(D[0][j], A0[kt], bf[j].x, bf[j].y);
                mma16816(D[1][j], A1[kt], bf[j].x, bf[j].y);
            }
        }
        // relu + fp16 pack -> next-layer A fragments (kt' = c)
#pragma unroll
        for (int m = 0; m < 2; m++) {
            uint32_t (*N)[4] = m ? N1 : N0;
            N[c][0] = pack_f16x2(fmaxf(D[m][0][0], 0.f), fmaxf(D[m][0][1], 0.f));
            N[c][1] = pack_f16x2(fmaxf(D[m][0][2], 0.f), fmaxf(D[m][0][3], 0.f));
            N[c][2] = pack_f16x2(fmaxf(D[m][1][0], 0.f), fmaxf(D[m][1][1], 0.f));
            N[c][3] = pack_f16x2(fmaxf(D[m][1][2], 0.f), fmaxf(D[m][1][3], 0.f));
        }
    }
}

__global__ __launch_bounds__(256, 1) void conv_kernel(
    const float* __restrict__ x, float* __restrict__ out)
{
    extern __shared__ __align__(16) char smem[];
    const float* bsm = (const float*)(smem + WS * 2);

    const int tid = threadIdx.x;
    const int w = tid >> 5, lane = tid & 31;
    const int gid = lane >> 2, tig = lane & 3;
    const int b  = blockIdx.x / 9;
    const int cs = blockIdx.x % 9;

    // stage all fragment-ordered weights (106496 B) + biases (2 KB)
    {
        const uint4* src = (const uint4*)(g_wh + (size_t)b * WS);
        uint4* dst = (uint4*)smem;
        for (int i = tid; i < WS / 8; i += 256) dst[i] = src[i];
        const float4* bsrc = (const float4*)(g_bias + b * 512);
        float4* bdst = (float4*)(smem + WS * 2);
        if (tid < 128) bdst[tid] = bsrc[tid];
    }
    __syncthreads();

    const float* xb = x + (size_t)b * FIN * HW;
    float* ob = out + (size_t)b * FOUT * HW;

    uint32_t X[2][4][4];
    uint32_t Abuf[2][2][8][4];   // ping-pong [pp][half][kt][4]

    for (int t = cs; t < 64; t += 9) {
        const int base = t * 256 + w * 32;

        // ---- load x as fp16 A fragments for both m16 halves ----
#pragma unroll
        for (int m = 0; m < 2; m++) {
            const int px_lo = base + m * 16 + gid;
            const int px_hi = px_lo + 8;
#pragma unroll
            for (int kt = 0; kt < 4; kt++) {
                const float* xp = xb + (size_t)(kt * 16 + tig * 2) * HW;
                X[m][kt][0] = pack_f16x2(xp[px_lo],          xp[HW + px_lo]);
                X[m][kt][1] = pack_f16x2(xp[px_hi],          xp[HW + px_hi]);
                X[m][kt][2] = pack_f16x2(xp[8 * HW + px_lo], xp[9 * HW + px_lo]);
                X[m][kt][3] = pack_f16x2(xp[8 * HW + px_hi], xp[9 * HW + px_hi]);
            }
        }

        // ---- layer in (KT=4): x -> Abuf[0] ----
        layer_fused<4>(X[0], X[1], Abuf[0][0], Abuf[0][1],
                       smem, WIN_O * 2, bsm + 0, lane, tig);
        // ---- layer mida (KT=8): Abuf[0] -> Abuf[1] ----
        layer_fused<8>(Abuf[0][0], Abuf[0][1], Abuf[1][0], Abuf[1][1],
                       smem, WMIDA_O * 2, bsm + 128, lane, tig);
        // ---- layer midb (KT=8): Abuf[1] -> Abuf[0] ----
        layer_fused<8>(Abuf[1][0], Abuf[1][1], Abuf[0][0], Abuf[0][1],
                       smem, WMIDB_O * 2, bsm + 256, lane, tig);

        // ---- out layer: Wout @ h + Wshort @ x, 64 ch, store ----
#pragma unroll
        for (int c = 0; c < 4; c++) {
            float D[2][2][4];
#pragma unroll
            for (int j = 0; j < 2; j++) {
                int ch = (c * 2 + j) * 8 + tig * 2;
                float b0 = bsm[384 + ch]     + bsm[448 + ch];
                float b1 = bsm[384 + ch + 1] + bsm[448 + ch + 1];
#pragma unroll
                for (int m = 0; m < 2; m++) {
                    D[m][j][0] = b0; D[m][j][1] = b1;
                    D[m][j][2] = b0; D[m][j][3] = b1;
                }
            }
#pragma unroll
            for (int kt = 0; kt < 8; kt++) {
                uint2 bf[2];
#pragma unroll
                for (int j = 0; j < 2; j++) {
                    int fo = (((c * 2 + j) * 8 + kt) * 32 + lane) * 8;
                    bf[j] = *(const uint2*)(smem + WOUT_O * 2 + fo);
                }
#pragma unroll
                for (int j = 0; j < 2; j++) {
                    mma16816(D[0][j], Abuf[0][0][kt], bf[j].x, bf[j].y);
                    mma16816(D[1][j], Abuf[0][1][kt], bf[j].x, bf[j].y);
                }
            }
#pragma unroll
            for (int kt = 0; kt < 4; kt++) {
                uint2 bf[2];
#pragma unroll
                for (int j = 0; j < 2; j++) {
                    int fo = (((c * 2 + j) * 4 + kt) * 32 + lane) * 8;
                    bf[j] = *(const uint2*)(smem + WSH_O * 2 + fo);
                }
#pragma unroll
                for (int j = 0; j < 2; j++) {
                    mma16816(D[0][j], X[0][kt], bf[j].x, bf[j].y);
                    mma16816(D[1][j], X[1][kt], bf[j].x, bf[j].y);
                }
            }
            // store 16 channels x 32 pixels
#pragma unroll
            for (int m = 0; m < 2; m++) {
                const int px_lo = base + m * 16 + gid;
                const int px_hi = px_lo + 8;
#pragma unroll
                for (int j = 0; j < 2; j++) {
                    int ch = (c * 2 + j) * 8 + tig * 2;
                    float* op = ob + (size_t)ch * HW;
                    op[px_lo]      = D[m][j][0];
                    op[HW + px_lo] = D[m][j][1];
                    op[px_hi]      = D[m][j][2];
                    op[HW + px_hi] = D[m][j][3];
                }
            }
        }
    }
}

// ============================================================
extern "C" void kernel_launch(void* const* d_in, const int* in_sizes, int n_in,
                              void* d_out, int out_size)
{
    (void)in_sizes; (void)n_in; (void)out_size;
    const float* x    = (const float*)d_in[0];
    const float* lat  = (const float*)d_in[1];
    const float* W    = (const float*)d_in[2];
    const float* bias = (const float*)d_in[3];
    float* out = (float*)d_out;

    hyper_kernel<<<KTOT / 128, 128>>>(lat, W, bias);

    cudaFuncSetAttribute(conv_kernel,
                         cudaFuncAttributeMaxDynamicSharedMemorySize, 110592);
    conv_kernel<<<16 * 9, 256, 110592>>>(x, out);
}